// round 12
// baseline (speedup 1.0000x reference)
#include <cuda_runtime.h>
#include <cuda_fp16.h>
#include <math.h>
#include <float.h>
#include <stdint.h>

#define NXY     36864      // 192*192 pixels
#define ETL     16
#define NDICT   4000
#define NSLOT   8          // SE (kept) columns; data-driven, padded with -1
#define REC_F   20         // floats per fp32 record (80 bytes, 2 atoms)
#define H_STRIDE 48        // bytes per fp16 record (32 w + 4 bias + pad)
#define NQ      8          // dictionary slices
#define NREC    250        // records per slice (500 atoms)
#define ATOMS_S (2 * NREC)
#define PX      2          // pixels per thread
#define TPB     256
#define GRPPX   (TPB * PX)      // 512 pixels per group
#define NGRP    (NXY / GRPPX)   // 72 pixel groups

#define BAND    2.5e-2f    // guaranteed bound on |fp16 score - fp32 score|

// Per-slice partial results: key = monotone(score)<<32 | (65535 - atom).
__device__ unsigned long long g_part[NQ * NXY];
// Arrival counters; atomicInc wraps at NQ -> self-resetting across replays.
__device__ unsigned int g_cnt[NGRP];

// ---- packed f32x2 helpers (Blackwell FFMA2 path) ------------------------
#define FMA_F32X2(d, a, b, c) \
    asm("fma.rn.f32x2 %0, %1, %2, %3;" : "=l"(d) : "l"(a), "l"(b), "l"(c))
#define PACK_F32X2(out, lo, hi) \
    asm("mov.b64 %0, {%1, %2};" : "=l"(out) : "f"(lo), "f"(hi))
#define UNPACK_F32X2(lo, hi, in) \
    asm("mov.b64 {%0, %1}, %2;" : "=f"(lo), "=f"(hi) : "l"(in))

__device__ __forceinline__ void get_cols(const float* __restrict__ delta_ms,
                                         int* cols) {
    int j = 0;
    for (int k = 0; k < ETL; k++) {
        if (delta_ms[k] * 1e-3f < 1e-3f && j < NSLOT) cols[j++] = k;
    }
    for (; j < NSLOT; j++) cols[j] = -1;
}

__device__ __forceinline__ unsigned int fmono(float f) {
    unsigned int u = __float_as_uint(f);
    return (u & 0x80000000u) ? ~u : (u | 0x80000000u);
}
__device__ __forceinline__ float fmono_inv(unsigned int u) {
    return (u & 0x80000000u) ? __uint_as_float(u ^ 0x80000000u)
                             : __uint_as_float(~u);
}

// exact fp32 (score_even, score_odd); bit-deterministic FMA chain order
// (identical to the chain every prior passing kernel used).
__device__ __forceinline__ void score2(
    ulonglong2 q0, ulonglong2 q1, ulonglong2 q2, ulonglong2 q3, uint64_t b,
    const uint64_t* sp, float& lo, float& hi)
{
    uint64_t acc = b;
    FMA_F32X2(acc, q0.x, sp[0], acc);
    FMA_F32X2(acc, q0.y, sp[1], acc);
    FMA_F32X2(acc, q1.x, sp[2], acc);
    FMA_F32X2(acc, q1.y, sp[3], acc);
    FMA_F32X2(acc, q2.x, sp[4], acc);
    FMA_F32X2(acc, q2.y, sp[5], acc);
    FMA_F32X2(acc, q3.x, sp[6], acc);
    FMA_F32X2(acc, q3.y, sp[7], acc);
    UNPACK_F32X2(lo, hi, acc);
}

__device__ __forceinline__ __half2 u2h2(unsigned int u) {
    __half2 h;
    *(unsigned int*)&h = u;
    return h;
}

// ---------------------------------------------------------------------------
// Single fused kernel. grid = 72 pixel-groups x 8 dict-slices = 576 CTAs,
// 2 CTAs/SM. fp16 screening scan (HFMA2, 2x fma throughput) with immediate
// exact-fp32 verification of any record within BAND of the running best.
// ---------------------------------------------------------------------------
__global__ void __launch_bounds__(TPB, 2) fused_kernel(
    const float* __restrict__ sig,       // [NXY, ETL]
    const float* __restrict__ db_mag,    // [NDICT, ETL]
    const float* __restrict__ t2s,       // [NDICT]
    const float* __restrict__ b1s,       // [NDICT]
    const float* __restrict__ delta_ms,  // [ETL]
    float* __restrict__ out)             // [3*NXY]: t2 | b1 | min_dist
{
    __shared__ __align__(16) float sdict32[NREC * REC_F];   // 20000 B
    __shared__ __align__(16) char  sdict16[NREC * H_STRIDE]; // 12000 B
    __shared__ int s_last;

    const int group = blockIdx.x >> 3;   // 0..71
    const int q     = blockIdx.x & 7;    // dict slice

    int cols[NSLOT];
    get_cols(delta_ms, cols);

    // ---- Build this slice's records: fp32 (exact) + fp16 (screen) ----
    for (int a = threadIdx.x; a < ATOMS_S; a += TPB) {
        int ga = q * ATOMS_S + a;        // global atom index
        float v[NSLOT];
        float n2 = 0.0f;
#pragma unroll
        for (int j = 0; j < NSLOT; j++) {
            int c = cols[j];
            float x = (c >= 0) ? db_mag[ga * ETL + c] : 0.0f;
            v[j] = x;
            n2 = fmaf(x, x, n2);
        }
        float inv = 0.0f;
        if (n2 > 0.0f) {
            float r = 1.0f / sqrtf(n2);
            if (isfinite(r)) inv = r;
        }
        int ri  = a >> 1;
        int par = a & 1;
        float* rec = sdict32 + ri * REC_F;
        __half* hrec = (__half*)(sdict16 + ri * H_STRIDE);
        float d2 = 0.0f;
#pragma unroll
        for (int j = 0; j < NSLOT; j++) {
            float s = v[j] * inv;
            float w = 2.0f * s;              // exact scaling by 2
            rec[2 * j + par] = w;
            hrec[2 * j + par] = __float2half(w);
            d2 = fmaf(s, s, d2);
        }
        rec[16 + par] = -d2;                  // fp32 bias
        hrec[16 + par] = __float2half(-d2);   // fp16 bias at byte 32/34
    }

    // ---- Load + normalize this thread's pixels (nan_to_num semantics) ----
    int n[PX];
    float s2px[PX];
    uint64_t sp[PX][NSLOT];       // fp32 (s,s) packs for exact verify
    __half2 sh[PX][NSLOT];        // fp16 (s,s) packs for screening
#pragma unroll
    for (int u = 0; u < PX; u++) {
        n[u] = group * GRPPX + u * TPB + threadIdx.x;
        float m[NSLOT];
        float nm2 = 0.0f;
#pragma unroll
        for (int j = 0; j < NSLOT; j++) {
            int c = cols[j];
            float v = (c >= 0) ? sig[n[u] * ETL + c] : 0.0f;
            m[j] = v;
            nm2 = fmaf(v, v, nm2);
        }
        float inv = 0.0f;
        if (nm2 > 0.0f) {
            float r = 1.0f / sqrtf(nm2);
            if (isfinite(r)) inv = r;
        }
        float acc = 0.0f;
#pragma unroll
        for (int j = 0; j < NSLOT; j++) {
            float s = m[j] * inv;
            acc = fmaf(s, s, acc);
            PACK_F32X2(sp[u][j], s, s);
            sh[u][j] = __half2half2(__float2half(s));
        }
        s2px[u] = acc;
    }

    __syncthreads();

    // ---- Screen scan (fp16) with inline exact verification ----
    float best[PX];
    int bidx[PX];
    __half th[PX];                // fp16 threshold = rd(best - BAND)
#pragma unroll
    for (int u = 0; u < PX; u++) {
        best[u] = -FLT_MAX;
        bidx[u] = 0;
        th[u] = __ushort_as_half(0xFC00);   // -inf: first record always verifies
    }

    const char* hbase = (const char*)sdict16;
    const char* base  = (const char*)sdict32;

#pragma unroll 1
    for (int i = 0; i < NREC; i++) {
        const uint4* hp = (const uint4*)(hbase + i * H_STRIDE);
        uint4 ha = hp[0];
        uint4 hb = hp[1];
        __half2 b2 = *(const __half2*)(hbase + i * H_STRIDE + 32);
        __half2 w0 = u2h2(ha.x), w1 = u2h2(ha.y), w2 = u2h2(ha.z), w3 = u2h2(ha.w);
        __half2 w4 = u2h2(hb.x), w5 = u2h2(hb.y), w6 = u2h2(hb.z), w7 = u2h2(hb.w);

        int trig = 0;
#pragma unroll
        for (int u = 0; u < PX; u++) {
            __half2 acc = b2;
            acc = __hfma2(w0, sh[u][0], acc);
            acc = __hfma2(w1, sh[u][1], acc);
            acc = __hfma2(w2, sh[u][2], acc);
            acc = __hfma2(w3, sh[u][3], acc);
            acc = __hfma2(w4, sh[u][4], acc);
            acc = __hfma2(w5, sh[u][5], acc);
            acc = __hfma2(w6, sh[u][6], acc);
            acc = __hfma2(w7, sh[u][7], acc);
            __half m = __hmax(__low2half(acc), __high2half(acc));
            trig |= (int)__hge(m, th[u]);
        }

        if (trig) {
            // exact fp32 rescore of this record for ALL pixels (order-safe)
            const ulonglong2* r = (const ulonglong2*)(base + i * 80);
            ulonglong2 q0 = r[0], q1 = r[1], q2 = r[2], q3 = r[3];
            uint64_t bb = *(const unsigned long long*)(base + i * 80 + 64);
#pragma unroll
            for (int u = 0; u < PX; u++) {
                float lo, hi;
                score2(q0, q1, q2, q3, bb, sp[u], lo, hi);
                if (lo > best[u]) { best[u] = lo; bidx[u] = 2 * i; }
                if (hi > best[u]) { best[u] = hi; bidx[u] = 2 * i + 1; }
                th[u] = __float2half_rd(best[u] - BAND);
            }
        }
    }

    // ---- Write partial key (exact fp32 best + first-index semantics) ----
    unsigned long long mykey[PX];
#pragma unroll
    for (int u = 0; u < PX; u++) {
        int atom = q * ATOMS_S + bidx[u];
        mykey[u] = ((unsigned long long)fmono(best[u]) << 32)
                 | (unsigned long long)(65535 - atom);
        g_part[q * NXY + n[u]] = mykey[u];
    }

    // ---- Arrival: last CTA of this pixel group merges ----
    __threadfence();
    __syncthreads();
    if (threadIdx.x == 0) {
        unsigned int old = atomicInc(&g_cnt[group], NQ - 1);  // wraps to 0
        s_last = (old == NQ - 1);
    }
    __syncthreads();
    if (!s_last) return;

    __threadfence();
#pragma unroll
    for (int u = 0; u < PX; u++) {
        unsigned long long key = mykey[u];
#pragma unroll
        for (int qq = 0; qq < NQ; qq++) {
            unsigned long long k2 = g_part[qq * NXY + n[u]];
            if (k2 > key) key = k2;   // ties: lower atom already wins in key
        }
        int atom = 65535 - (int)(key & 0xFFFFULL);
        float score = fmono_inv((unsigned int)(key >> 32));
        float dist2 = fmaxf(s2px[u] - score, 0.0f);
        out[n[u]]           = t2s[atom];
        out[NXY + n[u]]     = b1s[atom];
        out[2 * NXY + n[u]] = sqrtf(dist2);
    }
}

// ---------------------------------------------------------------------------
extern "C" void kernel_launch(void* const* d_in, const int* in_sizes, int n_in,
                              void* d_out, int out_size) {
    const float* slice_signal = (const float*)d_in[0];  // [192,192,16]
    const float* db_mag       = (const float*)d_in[1];  // [4000,16]
    const float* db_t2s_s     = (const float*)d_in[2];  // [4000]
    const float* db_b1s       = (const float*)d_in[3];  // [4000]
    const float* delta_ms     = (const float*)d_in[4];  // [16]
    float* out = (float*)d_out;

    fused_kernel<<<NGRP * NQ, TPB>>>(slice_signal, db_mag, db_t2s_s,
                                     db_b1s, delta_ms, out);
}

// round 13
// speedup vs baseline: 1.4223x; 1.4223x over previous
#include <cuda_runtime.h>
#include <math.h>
#include <float.h>
#include <stdint.h>

#define NXY     36864      // 192*192 pixels
#define ETL     16
#define NDICT   4000
#define NSLOT   8          // SE (kept) columns; data-driven, padded with -1
#define RECB    80         // bytes per record (2 atoms: 2x8 w + 2 bias + pad)
#define NQ      16         // dictionary slices
#define NREC    125        // records per slice (250 atoms)
#define ATOMS_S (2 * NREC)
#define PX      4          // pixels per thread
#define TPB     256
#define GRPPX   (TPB * PX)      // 1024 pixels per group
#define NGRP    (NXY / GRPPX)   // 36 pixel groups

// Per-slice partial results: key = monotone(score)<<32 | (65535 - atom).
__device__ unsigned long long g_part[NQ * NXY];
// Arrival counters; atomicInc wraps at NQ -> self-resetting across replays.
__device__ unsigned int g_cnt[NGRP];

// ---- packed f32x2 helpers (Blackwell FFMA2 path) ------------------------
#define FMA_F32X2(d, a, b, c) \
    asm("fma.rn.f32x2 %0, %1, %2, %3;" : "=l"(d) : "l"(a), "l"(b), "l"(c))
#define PACK_F32X2(out, lo, hi) \
    asm("mov.b64 %0, {%1, %2};" : "=l"(out) : "f"(lo), "f"(hi))
#define UNPACK_F32X2(lo, hi, in) \
    asm("mov.b64 {%0, %1}, %2;" : "=f"(lo), "=f"(hi) : "l"(in))

__device__ __forceinline__ void get_cols(const float* __restrict__ delta_ms,
                                         int* cols) {
    int j = 0;
    for (int k = 0; k < ETL; k++) {
        if (delta_ms[k] * 1e-3f < 1e-3f && j < NSLOT) cols[j++] = k;
    }
    for (; j < NSLOT; j++) cols[j] = -1;
}

__device__ __forceinline__ unsigned int fmono(float f) {
    unsigned int u = __float_as_uint(f);
    return (u & 0x80000000u) ? ~u : (u | 0x80000000u);
}
__device__ __forceinline__ float fmono_inv(unsigned int u) {
    return (u & 0x80000000u) ? __uint_as_float(u ^ 0x80000000u)
                             : __uint_as_float(~u);
}

// One atom's score: 4 two-lane FFMA2 partial sums + cross-lane combine.
// wq = atom's 4 packed (w_j, w_{j+1}); bias folded into lane-0 init.
// Bit-deterministic chain, identical in scan and recompute.
__device__ __forceinline__ float atom_score(
    ulonglong2 wA, ulonglong2 wB, float bias, const uint64_t* sp)
{
    uint64_t acc;
    PACK_F32X2(acc, bias, 0.0f);
    FMA_F32X2(acc, wA.x, sp[0], acc);
    FMA_F32X2(acc, wA.y, sp[1], acc);
    FMA_F32X2(acc, wB.x, sp[2], acc);
    FMA_F32X2(acc, wB.y, sp[3], acc);
    float lo, hi;
    UNPACK_F32X2(lo, hi, acc);
    return lo + hi;
}

// ---------------------------------------------------------------------------
// Single fused kernel. grid = 36 pixel-groups x 16 dict-slices = 576 CTAs,
// 3 CTAs/SM (<=83 regs, 10 KB SMEM) -> 24 warps/SM for latency coverage.
// Record (80 B): [0..32) atom-even w0..w7, [32..64) atom-odd w0..w7,
// [64..72) (bias_e, bias_o). Signal packs are true pairs (s_j, s_{j+1}).
// ---------------------------------------------------------------------------
__global__ void __launch_bounds__(TPB, 3) fused_kernel(
    const float* __restrict__ sig,       // [NXY, ETL]
    const float* __restrict__ db_mag,    // [NDICT, ETL]
    const float* __restrict__ t2s,       // [NDICT]
    const float* __restrict__ b1s,       // [NDICT]
    const float* __restrict__ delta_ms,  // [ETL]
    float* __restrict__ out)             // [3*NXY]: t2 | b1 | min_dist
{
    __shared__ __align__(16) float sdict[NREC * (RECB / 4)];   // 10 KB
    __shared__ int s_last;

    const int group = blockIdx.x >> 4;   // 0..35
    const int q     = blockIdx.x & 15;   // dict slice

    int cols[NSLOT];
    get_cols(delta_ms, cols);

    // ---- Build this slice's records (normalization == reference) ----
    for (int a = threadIdx.x; a < ATOMS_S; a += TPB) {
        int ga = q * ATOMS_S + a;        // global atom index
        float v[NSLOT];
        float n2 = 0.0f;
#pragma unroll
        for (int j = 0; j < NSLOT; j++) {
            int c = cols[j];
            float x = (c >= 0) ? db_mag[ga * ETL + c] : 0.0f;
            v[j] = x;
            n2 = fmaf(x, x, n2);
        }
        float inv = 0.0f;
        if (n2 > 0.0f) {
            float r = 1.0f / sqrtf(n2);
            if (isfinite(r)) inv = r;
        }
        float* rec = sdict + (a >> 1) * (RECB / 4);
        int par = a & 1;                  // 0 = even atom, 1 = odd atom
        float d2 = 0.0f;
#pragma unroll
        for (int j = 0; j < NSLOT; j++) {
            float s = v[j] * inv;
            rec[par * 8 + j] = 2.0f * s;  // w = 2 * normalized value
            d2 = fmaf(s, s, d2);
        }
        rec[16 + par] = -d2;              // bias
    }

    // ---- Load + normalize this thread's 4 pixels (nan_to_num semantics) ----
    uint64_t sp[PX][4];                   // (s0,s1),(s2,s3),(s4,s5),(s6,s7)
#pragma unroll
    for (int u = 0; u < PX; u++) {
        int n = group * GRPPX + u * TPB + threadIdx.x;
        float m[NSLOT];
        float nm2 = 0.0f;
#pragma unroll
        for (int j = 0; j < NSLOT; j++) {
            int c = cols[j];
            float v = (c >= 0) ? sig[n * ETL + c] : 0.0f;
            m[j] = v;
            nm2 = fmaf(v, v, nm2);
        }
        float inv = 0.0f;
        if (nm2 > 0.0f) {
            float r = 1.0f / sqrtf(nm2);
            if (isfinite(r)) inv = r;
        }
#pragma unroll
        for (int j = 0; j < 4; j++) {
            PACK_F32X2(sp[u][j], m[2 * j] * inv, m[2 * j + 1] * inv);
        }
    }

    __syncthreads();

    // ---- Scan: 125 records x (2 atoms) x 4 pixels ----
    float best[PX];
    int bit[PX];
#pragma unroll
    for (int u = 0; u < PX; u++) { best[u] = -FLT_MAX; bit[u] = 0; }

    const char* base = (const char*)sdict;
#pragma unroll 1
    for (int i = 0; i < NREC; i++) {
        const ulonglong2* r = (const ulonglong2*)(base + i * RECB);
        ulonglong2 eA = r[0], eB = r[1];     // even atom w-packs
        ulonglong2 oA = r[2], oB = r[3];     // odd atom w-packs
        float2 bias = *(const float2*)(base + i * RECB + 64);
#pragma unroll
        for (int u = 0; u < PX; u++) {
            float se = atom_score(eA, eB, bias.x, sp[u]);
            float so = atom_score(oA, oB, bias.y, sp[u]);
            float m = fmaxf(se, so);
            if (m > best[u]) { best[u] = m; bit[u] = i; }  // first rec wins
        }
    }

    // ---- Deterministic winner recompute -> write partial key ----
#pragma unroll
    for (int u = 0; u < PX; u++) {
        const ulonglong2* r = (const ulonglong2*)(base + bit[u] * RECB);
        ulonglong2 eA = r[0], eB = r[1], oA = r[2], oB = r[3];
        float2 bias = *(const float2*)(base + bit[u] * RECB + 64);
        float se = atom_score(eA, eB, bias.x, sp[u]);
        (void)se;
        int j = (se == best[u]) ? 0 : 1;  // even first: lower atom wins tie
        int atom = q * ATOMS_S + 2 * bit[u] + j;
        (void)oA; (void)oB;
        unsigned long long key =
            ((unsigned long long)fmono(best[u]) << 32)
            | (unsigned long long)(65535 - atom);
        int n = group * GRPPX + u * TPB + threadIdx.x;
        g_part[q * NXY + n] = key;
    }

    // ---- Arrival: last CTA of this pixel group merges ----
    __threadfence();
    __syncthreads();
    if (threadIdx.x == 0) {
        unsigned int old = atomicInc(&g_cnt[group], NQ - 1);  // wraps to 0
        s_last = (old == NQ - 1);
    }
    __syncthreads();
    if (!s_last) return;

    __threadfence();
#pragma unroll 1
    for (int u = 0; u < PX; u++) {
        int n = group * GRPPX + u * TPB + threadIdx.x;
        unsigned long long key = 0ULL;
#pragma unroll
        for (int qq = 0; qq < NQ; qq++) {
            unsigned long long k2 = g_part[qq * NXY + n];
            if (k2 > key) key = k2;   // ties: lower atom already wins in key
        }
        // recompute s2 for this pixel (cheap, merge CTA only)
        float nm2 = 0.0f;
        float m[NSLOT];
#pragma unroll
        for (int j = 0; j < NSLOT; j++) {
            int c = cols[j];
            float v = (c >= 0) ? sig[n * ETL + c] : 0.0f;
            m[j] = v;
            nm2 = fmaf(v, v, nm2);
        }
        float inv = 0.0f;
        if (nm2 > 0.0f) {
            float r = 1.0f / sqrtf(nm2);
            if (isfinite(r)) inv = r;
        }
        float s2 = 0.0f;
#pragma unroll
        for (int j = 0; j < NSLOT; j++) {
            float s = m[j] * inv;
            s2 = fmaf(s, s, s2);
        }
        int atom = 65535 - (int)(key & 0xFFFFULL);
        float score = fmono_inv((unsigned int)(key >> 32));
        float dist2 = fmaxf(s2 - score, 0.0f);
        out[n]           = t2s[atom];
        out[NXY + n]     = b1s[atom];
        out[2 * NXY + n] = sqrtf(dist2);
    }
}

// ---------------------------------------------------------------------------
extern "C" void kernel_launch(void* const* d_in, const int* in_sizes, int n_in,
                              void* d_out, int out_size) {
    const float* slice_signal = (const float*)d_in[0];  // [192,192,16]
    const float* db_mag       = (const float*)d_in[1];  // [4000,16]
    const float* db_t2s_s     = (const float*)d_in[2];  // [4000]
    const float* db_b1s       = (const float*)d_in[3];  // [4000]
    const float* delta_ms     = (const float*)d_in[4];  // [16]
    float* out = (float*)d_out;

    fused_kernel<<<NGRP * NQ, TPB>>>(slice_signal, db_mag, db_t2s_s,
                                     db_b1s, delta_ms, out);
}